// round 2
// baseline (speedup 1.0000x reference)
#include <cuda_runtime.h>

// Reverse cummax along axis 1 of [B=16, H=128, W=128, C=256] fp32.
// One thread per (b, w, c4) column, c4 = float4 group along C (64 per row).
// Loads/stores are fully coalesced (adjacent threads adjacent in C).
// Unroll-by-4 software pipeline: the 4 plane loads per iteration are
// independent -> MLP=4 per thread to cover DRAM latency.

#define B 16
#define H 128
#define W 128
#define C4 64                 // 256 floats / 4
#define PLANE4 (W * C4)       // float4 stride between consecutive h planes

__device__ __forceinline__ float4 f4max(float4 a, float4 b) {
    float4 r;
    r.x = fmaxf(a.x, b.x);
    r.y = fmaxf(a.y, b.y);
    r.z = fmaxf(a.z, b.z);
    r.w = fmaxf(a.w, b.w);
    return r;
}

__global__ __launch_bounds__(256)
void rev_cummax_kernel(const float4* __restrict__ in, float4* __restrict__ out) {
    int col = blockIdx.x * blockDim.x + threadIdx.x;   // 0 .. B*W*C4-1
    // col -> (b, w, c4)
    int b  = col / (W * C4);
    int r  = col - b * (W * C4);
    // base float4 index of (b, h=0, w, c4)
    long base = (long)b * H * PLANE4 + r;              // r == w*C4 + c4

    const float4* ip = in  + base + (long)(H - 1) * PLANE4;
    float4*       op = out + base + (long)(H - 1) * PLANE4;

    float4 run = make_float4(-__FLT_MAX__, -__FLT_MAX__, -__FLT_MAX__, -__FLT_MAX__);

    #pragma unroll 8
    for (int it = 0; it < H / 4; ++it) {
        // 4 independent loads (plane h, h-1, h-2, h-3)
        float4 v0 = ip[0];
        float4 v1 = ip[-PLANE4];
        float4 v2 = ip[-2 * PLANE4];
        float4 v3 = ip[-3 * PLANE4];

        run = f4max(run, v0);  op[0]           = run;
        run = f4max(run, v1);  op[-PLANE4]     = run;
        run = f4max(run, v2);  op[-2 * PLANE4] = run;
        run = f4max(run, v3);  op[-3 * PLANE4] = run;

        ip -= 4 * PLANE4;
        op -= 4 * PLANE4;
    }
}

extern "C" void kernel_launch(void* const* d_in, const int* in_sizes, int n_in,
                              void* d_out, int out_size) {
    const float4* in  = (const float4*)d_in[0];
    float4*       out = (float4*)d_out;
    int total_cols = B * W * C4;        // 131072 threads
    int threads = 256;
    int blocks  = total_cols / threads; // 512
    rev_cummax_kernel<<<blocks, threads>>>(in, out);
}

// round 3
// speedup vs baseline: 1.0024x; 1.0024x over previous
#include <cuda_runtime.h>

// Reverse cummax along axis 1 of [B=16, H=128, W=128, C=256] fp32.
// One thread per (b, w, c4) float4 column. Fully coalesced in both directions.
// Double-buffered software pipeline: 8 independent LDG.128 in flight per
// thread (prefetch next 4 planes while reducing/storing current 4).
// Streaming hints (__ldcs/__stcs): zero-reuse data, evict-first in L1/L2.

#define B 16
#define H 128
#define W 128
#define C4 64                 // 256 floats / 4
#define PLANE4 (W * C4)       // float4 stride between consecutive h planes

__device__ __forceinline__ float4 f4max(float4 a, float4 b) {
    float4 r;
    r.x = fmaxf(a.x, b.x);
    r.y = fmaxf(a.y, b.y);
    r.z = fmaxf(a.z, b.z);
    r.w = fmaxf(a.w, b.w);
    return r;
}

__global__ __launch_bounds__(256)
void rev_cummax_kernel(const float4* __restrict__ in, float4* __restrict__ out) {
    int col = blockIdx.x * blockDim.x + threadIdx.x;   // 0 .. B*W*C4-1
    int b  = col / (W * C4);
    int r  = col - b * (W * C4);
    long base = (long)b * H * PLANE4 + r;

    const float4* ip = in  + base + (long)(H - 1) * PLANE4;
    float4*       op = out + base + (long)(H - 1) * PLANE4;

    float4 run = make_float4(-__FLT_MAX__, -__FLT_MAX__, -__FLT_MAX__, -__FLT_MAX__);

    // Prologue: load first group of 4 planes (h = 127..124)
    float4 c0 = __ldcs(ip);
    float4 c1 = __ldcs(ip - PLANE4);
    float4 c2 = __ldcs(ip - 2 * PLANE4);
    float4 c3 = __ldcs(ip - 3 * PLANE4);

    #pragma unroll 1
    for (int it = 0; it < H / 4 - 1; ++it) {
        // Prefetch next group (independent of current group's consumption)
        const float4* np = ip - 4 * PLANE4;
        float4 n0 = __ldcs(np);
        float4 n1 = __ldcs(np - PLANE4);
        float4 n2 = __ldcs(np - 2 * PLANE4);
        float4 n3 = __ldcs(np - 3 * PLANE4);

        // Consume current group
        run = f4max(run, c0);  __stcs(op,              run);
        run = f4max(run, c1);  __stcs(op - PLANE4,     run);
        run = f4max(run, c2);  __stcs(op - 2 * PLANE4, run);
        run = f4max(run, c3);  __stcs(op - 3 * PLANE4, run);

        c0 = n0; c1 = n1; c2 = n2; c3 = n3;
        ip = np;
        op -= 4 * PLANE4;
    }

    // Epilogue: consume last group (h = 3..0)
    run = f4max(run, c0);  __stcs(op,              run);
    run = f4max(run, c1);  __stcs(op - PLANE4,     run);
    run = f4max(run, c2);  __stcs(op - 2 * PLANE4, run);
    run = f4max(run, c3);  __stcs(op - 3 * PLANE4, run);
}

extern "C" void kernel_launch(void* const* d_in, const int* in_sizes, int n_in,
                              void* d_out, int out_size) {
    const float4* in  = (const float4*)d_in[0];
    float4*       out = (float4*)d_out;
    int total_cols = B * W * C4;        // 131072 threads
    int threads = 256;
    int blocks  = total_cols / threads; // 512 CTAs — all resident in one wave
    rev_cummax_kernel<<<blocks, threads>>>(in, out);
}

// round 17
// speedup vs baseline: 1.0226x; 1.0201x over previous
#include <cuda_runtime.h>

// Reverse cummax along axis 1 of [B=16, H=128, W=128, C=256] fp32.
// One thread per (b, w, c2) float2 column -> 262144 threads, 1024 CTAs.
//   * 1024/148 = 6.92 CTAs/SM: near-perfect wave balance (vs 3.46 before)
//   * occupancy ~81% (1770 thr/SM) doubles warp-level latency tolerance
// Coalescing unchanged: warp covers 256 contiguous bytes per plane step.
// Double-buffered 4-plane pipeline; streaming cache hints (zero reuse).

#define B 16
#define H 128
#define W 128
#define C2 128                // 256 floats / 2
#define PLANE2 (W * C2)       // float2 stride between consecutive h planes

__device__ __forceinline__ float2 f2max(float2 a, float2 b) {
    float2 r;
    r.x = fmaxf(a.x, b.x);
    r.y = fmaxf(a.y, b.y);
    return r;
}

__global__ __launch_bounds__(256)
void rev_cummax_kernel(const float2* __restrict__ in, float2* __restrict__ out) {
    int col = blockIdx.x * blockDim.x + threadIdx.x;   // 0 .. B*W*C2-1
    int b  = col / (W * C2);
    int r  = col - b * (W * C2);
    long base = (long)b * H * PLANE2 + r;

    const float2* ip = in  + base + (long)(H - 1) * PLANE2;
    float2*       op = out + base + (long)(H - 1) * PLANE2;

    float2 run = make_float2(-__FLT_MAX__, -__FLT_MAX__);

    // Prologue: first group of 4 planes (h = 127..124)
    float2 c0 = __ldcs(ip);
    float2 c1 = __ldcs(ip - PLANE2);
    float2 c2 = __ldcs(ip - 2 * PLANE2);
    float2 c3 = __ldcs(ip - 3 * PLANE2);

    #pragma unroll 1
    for (int it = 0; it < H / 4 - 1; ++it) {
        const float2* np = ip - 4 * PLANE2;
        float2 n0 = __ldcs(np);
        float2 n1 = __ldcs(np - PLANE2);
        float2 n2 = __ldcs(np - 2 * PLANE2);
        float2 n3 = __ldcs(np - 3 * PLANE2);

        run = f2max(run, c0);  __stcs(op,              run);
        run = f2max(run, c1);  __stcs(op - PLANE2,     run);
        run = f2max(run, c2);  __stcs(op - 2 * PLANE2, run);
        run = f2max(run, c3);  __stcs(op - 3 * PLANE2, run);

        c0 = n0; c1 = n1; c2 = n2; c3 = n3;
        ip = np;
        op -= 4 * PLANE2;
    }

    // Epilogue (h = 3..0)
    run = f2max(run, c0);  __stcs(op,              run);
    run = f2max(run, c1);  __stcs(op - PLANE2,     run);
    run = f2max(run, c2);  __stcs(op - 2 * PLANE2, run);
    run = f2max(run, c3);  __stcs(op - 3 * PLANE2, run);
}

extern "C" void kernel_launch(void* const* d_in, const int* in_sizes, int n_in,
                              void* d_out, int out_size) {
    const float2* in  = (const float2*)d_in[0];
    float2*       out = (float2*)d_out;
    int total_cols = B * W * C2;        // 262144 threads
    int threads = 256;
    int blocks  = total_cols / threads; // 1024 CTAs
    rev_cummax_kernel<<<blocks, threads>>>(in, out);
}